// round 8
// baseline (speedup 1.0000x reference)
#include <cuda_runtime.h>
#include <cstdint>

#define NPIX  1600
#define WIDTH 40
#define HID   64
#define TI    64       // i-tile
#define TJ    32       // j-tile
#define ST    66       // smem row stride (floats): LDS.64 bank-conflict-free
#define OT    36       // out staging stride

typedef unsigned long long u64;

// ---- packed f32x2 helpers ----
static __device__ __forceinline__ u64 add2(u64 a, u64 b) {
    u64 r; asm("add.rn.f32x2 %0, %1, %2;" : "=l"(r) : "l"(a), "l"(b)); return r;
}
static __device__ __forceinline__ u64 fma2(u64 a, u64 b, u64 c) {
    u64 r; asm("fma.rn.f32x2 %0, %1, %2, %3;" : "=l"(r) : "l"(a), "l"(b), "l"(c)); return r;
}
static __device__ __forceinline__ float2 up2(u64 v) {
    float2 r; asm("mov.b64 {%0, %1}, %2;" : "=f"(r.x), "=f"(r.y) : "l"(v)); return r;
}
static __device__ __forceinline__ u64 pk2(float a, float b) {
    u64 r; asm("mov.b64 %0, {%1, %2};" : "=l"(r) : "f"(a), "f"(b)); return r;
}
static __device__ __forceinline__ u64 relu2(u64 v) {
    float2 t = up2(v);
    return pk2(fmaxf(t.x, 0.0f), fmaxf(t.y, 0.0f));
}

// ---------------------------------------------------------------------------
// fully fused: each block independently computes s / C[h] / its U,V rows in
// smem, then the 64x32 tile. ONE launch, no globals, no inter-block sync.
// ---------------------------------------------------------------------------
__global__ void __launch_bounds__(128, 8) rpe_fused_kernel(
    float* __restrict__ out,
    const int*   __restrict__ qmod_p,
    const int*   __restrict__ kmod_p,
    const float* __restrict__ smap,      // (4,1,80,80)
    const float* __restrict__ memb,      // (3,16)
    const float* __restrict__ W1,        // (36,64)
    const float* __restrict__ b1,        // (64,)
    const float* __restrict__ W2,        // (64,)
    const float* __restrict__ b2)        // (1,)
{
    __shared__ float Us[TI * ST];        // 16896 B
    __shared__ float Vs[TJ * ST];        //  8448 B
    __shared__ float w2s[HID];           //   256 B
    __shared__ float Cs[HID];            //   256 B
    __shared__ float mv[32];             //   128 B
    __shared__ float sU[TI], xU[TI], yU[TI];   // 768 B
    __shared__ float sV[TJ], xV[TJ], yV[TJ];   // 384 B
    // total 27136 B -> 8 blocks/SM = 217 KB

    const int tid = threadIdx.x;
    const int i0 = blockIdx.y * TI;
    const int j0 = blockIdx.x * TJ;
    const float raw[4] = {0.25f, 0.75f, 0.75f, 0.25f};

    // ---- phase A: per-pixel s (antialiased resize 80->40, batch mean) ----
    if (tid < 96) {
        const int n = (tid < 64) ? (i0 + tid) : (j0 + tid - 64);
        const int r = n / WIDTH, c = n % WIDTH;
        float sy = 0.f, sx = 0.f;
        float wy[4], wx[4];
        #pragma unroll
        for (int t = 0; t < 4; t++) {
            int iy = 2 * r - 1 + t;
            wy[t] = (iy >= 0 && iy < 80) ? raw[t] : 0.f;  sy += wy[t];
            int ix = 2 * c - 1 + t;
            wx[t] = (ix >= 0 && ix < 80) ? raw[t] : 0.f;  sx += wx[t];
        }
        float acc = 0.f;
        #pragma unroll
        for (int b = 0; b < 4; b++) {
            const float* base = smap + b * 6400;
            #pragma unroll
            for (int ty = 0; ty < 4; ty++) {
                if (wy[ty] == 0.f) continue;
                int iy = 2 * r - 1 + ty;
                float rowacc = 0.f;
                #pragma unroll
                for (int tx = 0; tx < 4; tx++) {
                    if (wx[tx] == 0.f) continue;
                    rowacc += wx[tx] * base[iy * 80 + (2 * c - 1 + tx)];
                }
                acc += wy[ty] * rowacc;
            }
        }
        const float s = acc / (sy * sx) * 0.25f;
        const float x = (float)c * (1.0f / 39.0f) - 0.5f;
        const float y = (float)r * (1.0f / 39.0f) - 0.5f;
        if (tid < 64) { sU[tid] = s; xU[tid] = x; yU[tid] = y; }
        else          { int p = tid - 64; sV[p] = s; xV[p] = x; yV[p] = y; }
    } else {
        const int t = tid - 96;                      // 0..31: modality vector
        const int m = (t < 16) ? *qmod_p : *kmod_p;
        mv[t] = memb[m * 16 + (t & 15)];
    }
    __syncthreads();

    // ---- phase B: C[h] = mod_vec @ W_mod + b1 ; stage w2 ----
    if (tid < HID) {
        float cc = b1[tid];
        #pragma unroll
        for (int k = 0; k < 32; k++)
            cc += mv[k] * W1[(2 + k) * HID + tid];
        Cs[tid] = cc;
    } else if (tid < 80) {
        int t = tid - 64;
        *(float4*)&w2s[t * 4] = *(const float4*)&W2[t * 4];
    }
    __syncthreads();

    // ---- phase C: generate U (64 rows) and V (32 rows) into smem ----
    {
        const int hh = tid & 63, half = tid >> 6;
        const float w0  = W1[hh];
        const float w1  = W1[HID + hh];
        const float wsi = W1[34 * HID + hh];
        const float wsj = W1[35 * HID + hh];
        const float ch  = Cs[hh];
        #pragma unroll
        for (int k = 0; k < 32; k++) {
            int r = half * 32 + k;
            Us[r * ST + hh] = xU[r] * w0 + yU[r] * w1 + sU[r] * wsi + ch;
        }
        #pragma unroll
        for (int k = 0; k < 16; k++) {
            int r = half * 16 + k;
            Vs[r * ST + hh] = -(xV[r] * w0 + yV[r] * w1) + sV[r] * wsj;
        }
    }
    const float b2v = *b2;
    __syncthreads();

    // ---- main loop: 4i x 4j per thread, packed f32x2 over h-pairs ----
    const int ig = tid & 15;    // i = ig + 16a, a<4
    const int jg = tid >> 4;    // j = jg + 8b,  b<4

    u64 acc[4][4];
    #pragma unroll
    for (int a = 0; a < 4; a++)
        #pragma unroll
        for (int b = 0; b < 4; b++) acc[a][b] = 0ull;

    #pragma unroll 1
    for (int h = 0; h < HID; h += 2) {
        u64 w = *(const u64*)&w2s[h];
        u64 u[4], v[4];
        #pragma unroll
        for (int a = 0; a < 4; a++)
            u[a] = *(const u64*)&Us[(ig + 16 * a) * ST + h];
        #pragma unroll
        for (int b = 0; b < 4; b++)
            v[b] = *(const u64*)&Vs[(jg + 8 * b) * ST + h];
        #pragma unroll
        for (int a = 0; a < 4; a++)
            #pragma unroll
            for (int b = 0; b < 4; b++)
                acc[a][b] = fma2(relu2(add2(u[a], v[b])), w, acc[a][b]);
    }
    __syncthreads();   // done reading Us before reuse as staging

    // ---- epilogue: horizontal add, smem stage, coalesced float4 stores ----
    float* outS = Us;   // 64*36 = 2304 floats <= 64*66
    #pragma unroll
    for (int a = 0; a < 4; a++)
        #pragma unroll
        for (int b = 0; b < 4; b++) {
            float2 p = up2(acc[a][b]);
            outS[(ig + 16 * a) * OT + (jg + 8 * b)] = p.x + p.y + b2v;
        }
    __syncthreads();
    #pragma unroll
    for (int k = tid; k < TI * 8; k += 128) {
        int r = k >> 3, c4 = (k & 7) << 2;
        *(float4*)&out[(u64)(i0 + r) * NPIX + j0 + c4] = *(const float4*)&outS[r * OT + c4];
    }
}

// ---------------------------------------------------------------------------
extern "C" void kernel_launch(void* const* d_in, const int* in_sizes, int n_in,
                              void* d_out, int out_size) {
    // 0:h 1:w 2:q_mod 3:k_mod 4:structure_map 5:mod_embed 6:W1 7:b1 8:W2 9:b2
    const int*   qmod = (const int*)d_in[2];
    const int*   kmod = (const int*)d_in[3];
    const float* smap = (const float*)d_in[4];
    const float* memb = (const float*)d_in[5];
    const float* W1   = (const float*)d_in[6];
    const float* b1   = (const float*)d_in[7];
    const float* W2   = (const float*)d_in[8];
    const float* b2   = (const float*)d_in[9];
    float* out = (float*)d_out;

    dim3 grid(NPIX / TJ, NPIX / TI);   // 50 x 25 = 1250 blocks
    rpe_fused_kernel<<<grid, 128>>>(out, qmod, kmod, smap, memb, W1, b1, W2, b2);
}

// round 9
// speedup vs baseline: 1.0067x; 1.0067x over previous
#include <cuda_runtime.h>
#include <cstdint>

#define NPIX  1600
#define WIDTH 40
#define HID   64
#define TI    64
#define TJ    32
#define ST    68       // smem row stride (floats): conflict-free LDS.128
#define OT    36       // out staging stride
#define NPREP 50
#define NTILES 1250    // 25 x 50

typedef unsigned long long u64;

// persistent scratch (allocation-free rule)
__device__ float g_U[NPIX][HID];
__device__ float g_V[NPIX][HID];
__device__ int   g_done   = 0;
__device__ int   g_passed = 0;

// ---- packed f32x2 helpers ----
static __device__ __forceinline__ u64 add2(u64 a, u64 b) {
    u64 r; asm("add.rn.f32x2 %0, %1, %2;" : "=l"(r) : "l"(a), "l"(b)); return r;
}
static __device__ __forceinline__ u64 fma2(u64 a, u64 b, u64 c) {
    u64 r; asm("fma.rn.f32x2 %0, %1, %2, %3;" : "=l"(r) : "l"(a), "l"(b), "l"(c)); return r;
}
static __device__ __forceinline__ float2 up2(u64 v) {
    float2 r; asm("mov.b64 {%0, %1}, %2;" : "=f"(r.x), "=f"(r.y) : "l"(v)); return r;
}
static __device__ __forceinline__ u64 pk2(float a, float b) {
    u64 r; asm("mov.b64 %0, {%1, %2};" : "=l"(r) : "f"(a), "f"(b)); return r;
}
static __device__ __forceinline__ u64 relu2(u64 v) {
    float2 t = up2(v);
    return pk2(fmaxf(t.x, 0.0f), fmaxf(t.y, 0.0f));
}
static __device__ __forceinline__ uint32_t s2u(const void* p) {
    return (uint32_t)__cvta_generic_to_shared(p);
}
static __device__ __forceinline__ void cpa16(uint32_t dst, const void* src) {
    asm volatile("cp.async.cg.shared.global [%0], [%1], 16;" :: "r"(dst), "l"(src));
}
static __device__ __forceinline__ int ld_acq(const int* p) {
    int v; asm volatile("ld.global.acquire.gpu.b32 %0, [%1];" : "=r"(v) : "l"(p)); return v;
}

// ---------------------------------------------------------------------------
// single fused kernel: blocks 0..49 shard the global prep (32 pixels each),
// everyone gates on g_done==50, then all 1250 blocks compute one 64x32 tile.
// ---------------------------------------------------------------------------
__global__ void __launch_bounds__(128, 8) rpe_fused_kernel(
    float* __restrict__ out,
    const int*   __restrict__ qmod_p,
    const int*   __restrict__ kmod_p,
    const float* __restrict__ smap,      // (4,1,80,80)
    const float* __restrict__ memb,      // (3,16)
    const float* __restrict__ W1,        // (36,64)
    const float* __restrict__ b1,        // (64,)
    const float* __restrict__ W2,        // (64,)
    const float* __restrict__ b2)        // (1,)
{
    __shared__ float Us[TI * ST];        // 17408 B
    __shared__ float Vs[TJ * ST];        //  8704 B
    __shared__ float w2s[HID];           //   256 B
    // prep-only scratch (union-able but small):
    __shared__ float part[32][5];
    __shared__ float s_sh[32];
    __shared__ float mv[32];
    __shared__ float Cs[HID];

    const int bt  = blockIdx.x;          // 0..1249
    const int tid = threadIdx.x;
    const float raw[4] = {0.25f, 0.75f, 0.75f, 0.25f};

    // ================= prep shard (blocks 0..49) =================
    if (bt < NPREP) {
        const int n0 = bt * 32;

        if (tid < 32) {
            int m = (tid < 16) ? *qmod_p : *kmod_p;
            mv[tid] = memb[m * 16 + (tid & 15)];
        }
        {   // antialiased resize taps: one (pixel,batch) per thread
            const int pix = tid >> 2, bb = tid & 3;
            const int n = n0 + pix;
            const int r = n / WIDTH, c = n % WIDTH;
            const float* base = smap + bb * 6400;
            float acc = 0.f;
            #pragma unroll
            for (int ty = 0; ty < 4; ty++) {
                int iy = 2 * r - 1 + ty;
                if (iy < 0 || iy >= 80) continue;
                #pragma unroll
                for (int tx = 0; tx < 4; tx++) {
                    int ix = 2 * c - 1 + tx;
                    if (ix < 0 || ix >= 80) continue;
                    acc += raw[ty] * raw[tx] * base[iy * 80 + ix];
                }
            }
            part[pix][bb] = acc;
        }
        __syncthreads();

        if (tid < HID) {                  // C[h] = mod_vec @ W_mod + b1
            float cc = b1[tid];
            #pragma unroll
            for (int k = 0; k < 32; k++)
                cc += mv[k] * W1[(2 + k) * HID + tid];
            Cs[tid] = cc;
        } else if (tid < 96) {            // finalize s (edge renorm, batch mean)
            const int p = tid - 64;
            const int n = n0 + p;
            const int r = n / WIDTH, c = n % WIDTH;
            float sy = 0.f, sx = 0.f;
            #pragma unroll
            for (int q = 0; q < 4; q++) {
                int iy = 2 * r - 1 + q; if (iy >= 0 && iy < 80) sy += raw[q];
                int ix = 2 * c - 1 + q; if (ix >= 0 && ix < 80) sx += raw[q];
            }
            s_sh[p] = (part[p][0] + part[p][1] + part[p][2] + part[p][3])
                      / (sy * sx) * 0.25f;
        }
        __syncthreads();

        {   // write U and V rows (h-coalesced)
            const int hh = tid & 63, ng = tid >> 6;
            const float w0  = W1[hh];
            const float w1  = W1[HID + hh];
            const float wsi = W1[34 * HID + hh];
            const float wsj = W1[35 * HID + hh];
            const float ch  = Cs[hh];
            #pragma unroll
            for (int k = 0; k < 16; k++) {
                int nn = ng * 16 + k;
                int n = n0 + nn;
                int r = n / WIDTH, c = n % WIDTH;
                float x = (float)c * (1.0f / 39.0f) - 0.5f;
                float y = (float)r * (1.0f / 39.0f) - 0.5f;
                float s = s_sh[nn];
                float xy = x * w0 + y * w1;
                g_U[n][hh] =  xy + s * wsi + ch;
                g_V[n][hh] = -xy + s * wsj;
            }
        }
        __threadfence();
        __syncthreads();
        if (tid == 0) atomicAdd(&g_done, 1);    // release (after fence)
    }

    // ================= gate =================
    if (tid == 0) {
        while (ld_acq(&g_done) < NPREP) __nanosleep(128);
        int p = atomicAdd(&g_passed, 1);
        if (p == NTILES - 1) {              // last pass resets for next replay
            atomicExch(&g_done, 0);
            atomicExch(&g_passed, 0);
        }
    }
    __syncthreads();

    // ================= main tile =================
    const int i0 = (bt / 50) * TI;
    const int j0 = (bt % 50) * TJ;

    #pragma unroll
    for (int k = tid; k < TI * 16; k += 128) {
        int r = k >> 4, c4 = (k & 15) << 2;
        cpa16(s2u(&Us[r * ST + c4]), &g_U[i0 + r][c4]);
    }
    #pragma unroll
    for (int k = tid; k < TJ * 16; k += 128) {
        int r = k >> 4, c4 = (k & 15) << 2;
        cpa16(s2u(&Vs[r * ST + c4]), &g_V[j0 + r][c4]);
    }
    if (tid < 16)
        cpa16(s2u(&w2s[tid * 4]), &W2[tid * 4]);
    asm volatile("cp.async.commit_group;");
    const float b2v = *b2;
    asm volatile("cp.async.wait_group 0;");
    __syncthreads();

    const int ig = tid & 15;    // i = ig + 16a, a<4
    const int jg = tid >> 4;    // j = jg + 8b,  b<4

    u64 acc[4][4];
    #pragma unroll
    for (int a = 0; a < 4; a++)
        #pragma unroll
        for (int b = 0; b < 4; b++) acc[a][b] = 0ull;

    #pragma unroll 2
    for (int h = 0; h < HID; h += 4) {
        ulonglong2 w = *(const ulonglong2*)&w2s[h];
        ulonglong2 u[4], v[4];
        #pragma unroll
        for (int a = 0; a < 4; a++)
            u[a] = *(const ulonglong2*)&Us[(ig + 16 * a) * ST + h];
        #pragma unroll
        for (int b = 0; b < 4; b++)
            v[b] = *(const ulonglong2*)&Vs[(jg + 8 * b) * ST + h];
        #pragma unroll
        for (int a = 0; a < 4; a++)
            #pragma unroll
            for (int b = 0; b < 4; b++) {
                acc[a][b] = fma2(relu2(add2(u[a].x, v[b].x)), w.x, acc[a][b]);
                acc[a][b] = fma2(relu2(add2(u[a].y, v[b].y)), w.y, acc[a][b]);
            }
    }
    __syncthreads();   // done reading Us before reuse as staging

    float* outS = Us;   // 64*36 = 2304 floats <= 64*68
    #pragma unroll
    for (int a = 0; a < 4; a++)
        #pragma unroll
        for (int b = 0; b < 4; b++) {
            float2 p = up2(acc[a][b]);
            outS[(ig + 16 * a) * OT + (jg + 8 * b)] = p.x + p.y + b2v;
        }
    __syncthreads();
    #pragma unroll
    for (int k = tid; k < TI * 8; k += 128) {
        int r = k >> 3, c4 = (k & 7) << 2;
        *(float4*)&out[(u64)(i0 + r) * NPIX + j0 + c4] = *(const float4*)&outS[r * OT + c4];
    }
}

// ---------------------------------------------------------------------------
extern "C" void kernel_launch(void* const* d_in, const int* in_sizes, int n_in,
                              void* d_out, int out_size) {
    // 0:h 1:w 2:q_mod 3:k_mod 4:structure_map 5:mod_embed 6:W1 7:b1 8:W2 9:b2
    const int*   qmod = (const int*)d_in[2];
    const int*   kmod = (const int*)d_in[3];
    const float* smap = (const float*)d_in[4];
    const float* memb = (const float*)d_in[5];
    const float* W1   = (const float*)d_in[6];
    const float* b1   = (const float*)d_in[7];
    const float* W2   = (const float*)d_in[8];
    const float* b2   = (const float*)d_in[9];
    float* out = (float*)d_out;

    rpe_fused_kernel<<<NTILES, 128>>>(out, qmod, kmod, smap, memb, W1, b1, W2, b2);
}

// round 11
// speedup vs baseline: 1.1480x; 1.1404x over previous
#include <cuda_runtime.h>
#include <cstdint>

#define NPIX  1600
#define WIDTH 40
#define HID   64
#define TI    64
#define TJ    32
#define ST    68       // 272B rows: 16B-aligned for cp.async; LDS.64 bank-pair stride 2*ig -> conflict-free
#define OT    36
#define NTJ   50

typedef unsigned long long u64;

__device__ float g_U[NPIX][HID];
__device__ float g_V[NPIX][HID];

// ---- packed f32x2 helpers ----
static __device__ __forceinline__ u64 add2(u64 a, u64 b) {
    u64 r; asm("add.rn.f32x2 %0, %1, %2;" : "=l"(r) : "l"(a), "l"(b)); return r;
}
static __device__ __forceinline__ u64 fma2(u64 a, u64 b, u64 c) {
    u64 r; asm("fma.rn.f32x2 %0, %1, %2, %3;" : "=l"(r) : "l"(a), "l"(b), "l"(c)); return r;
}
static __device__ __forceinline__ float2 up2(u64 v) {
    float2 r; asm("mov.b64 {%0, %1}, %2;" : "=f"(r.x), "=f"(r.y) : "l"(v)); return r;
}
static __device__ __forceinline__ u64 pk2(float a, float b) {
    u64 r; asm("mov.b64 %0, {%1, %2};" : "=l"(r) : "f"(a), "f"(b)); return r;
}
static __device__ __forceinline__ u64 relu2(u64 v) {
    float2 t = up2(v);
    return pk2(fmaxf(t.x, 0.0f), fmaxf(t.y, 0.0f));
}
static __device__ __forceinline__ uint32_t s2u(const void* p) {
    return (uint32_t)__cvta_generic_to_shared(p);
}
static __device__ __forceinline__ void cpa16(uint32_t dst, const void* src) {
    asm volatile("cp.async.cg.shared.global [%0], [%1], 16;" :: "r"(dst), "l"(src));
}
// LDS.64 with register base + immediate byte offset
static __device__ __forceinline__ u64 lds64(uint32_t base, int imm) {
    u64 r; asm("ld.shared.b64 %0, [%1];" : "=l"(r) : "r"(base + imm)); return r;
}

// ---------------------------------------------------------------------------
// prep: 100 blocks x 128 threads, 16 pixels each.
// ---------------------------------------------------------------------------
__global__ void __launch_bounds__(128) prep_kernel(
    const int* __restrict__ qmod_p, const int* __restrict__ kmod_p,
    const float* __restrict__ smap,      // (4,1,80,80)
    const float* __restrict__ memb,      // (3,16)
    const float* __restrict__ W1,        // (36,64)
    const float* __restrict__ b1)        // (64,)
{
    __shared__ float part[16][5];
    __shared__ float s_sh[16];
    __shared__ float mv[32];
    __shared__ float Cs[HID];

    const int tid = threadIdx.x;
    const int n0  = blockIdx.x * 16;
    const float raw[4] = {0.25f, 0.75f, 0.75f, 0.25f};

    if (tid >= 64 && tid < 96) {
        int t = tid - 64;
        int m = (t < 16) ? *qmod_p : *kmod_p;
        mv[t] = memb[m * 16 + (t & 15)];
    }

    if (tid < 64) {   // one (pixel,batch) per thread, 16 taps
        const int pix = tid >> 2, bb = tid & 3;
        const int n = n0 + pix;
        const int r = n / WIDTH, c = n % WIDTH;
        const float* base = smap + bb * 6400;
        float acc = 0.f;
        #pragma unroll
        for (int ty = 0; ty < 4; ty++) {
            int iy = 2 * r - 1 + ty;
            if (iy < 0 || iy >= 80) continue;
            #pragma unroll
            for (int tx = 0; tx < 4; tx++) {
                int ix = 2 * c - 1 + tx;
                if (ix < 0 || ix >= 80) continue;
                acc += raw[ty] * raw[tx] * base[iy * 80 + ix];
            }
        }
        part[pix][bb] = acc;
    }
    __syncthreads();

    if (tid < HID) {                      // C[h]
        float cc = b1[tid];
        #pragma unroll
        for (int k = 0; k < 32; k++)
            cc += mv[k] * W1[(2 + k) * HID + tid];
        Cs[tid] = cc;
    } else if (tid < 80) {                // finalize s (edge renorm, batch mean)
        const int p = tid - 64;
        const int n = n0 + p;
        const int r = n / WIDTH, c = n % WIDTH;
        float sy = 0.f, sx = 0.f;
        #pragma unroll
        for (int q = 0; q < 4; q++) {
            int iy = 2 * r - 1 + q; if (iy >= 0 && iy < 80) sy += raw[q];
            int ix = 2 * c - 1 + q; if (ix >= 0 && ix < 80) sx += raw[q];
        }
        s_sh[p] = (part[p][0] + part[p][1] + part[p][2] + part[p][3])
                  / (sy * sx) * 0.25f;
    }
    __syncthreads();

    // U and V: hh = tid&63 spans h (coalesced), 8 n's per thread
    {
        const int hh = tid & 63, ng = tid >> 6;
        const float w0  = W1[hh];
        const float w1  = W1[HID + hh];
        const float wsi = W1[34 * HID + hh];
        const float wsj = W1[35 * HID + hh];
        const float ch  = Cs[hh];
        #pragma unroll
        for (int k = 0; k < 8; k++) {
            int nn = ng * 8 + k;
            int n = n0 + nn;
            int r = n / WIDTH, c = n % WIDTH;
            float x = (float)c * (1.0f / 39.0f) - 0.5f;
            float y = (float)r * (1.0f / 39.0f) - 0.5f;
            float s = s_sh[nn];
            float xy = x * w0 + y * w1;
            g_U[n][hh] =  xy + s * wsi + ch;
            g_V[n][hh] = -xy + s * wsj;
        }
    }
}

// ---------------------------------------------------------------------------
// main: 64x32 tile, 128 threads, 4i x 4j per thread, packed f32x2 over h-pairs.
// u64 LDS with immediate offsets; 8 blocks/SM.
// ---------------------------------------------------------------------------
__global__ void __launch_bounds__(128, 8) rpe_main_kernel(
    float* __restrict__ out,
    const float* __restrict__ W2,    // (64,)
    const float* __restrict__ b2)    // (1,)
{
    __shared__ float Us[TI * ST];    // 17408 B
    __shared__ float Vs[TJ * ST];    //  8704 B
    __shared__ float w2s[HID];       //   256 B

    const int tid = threadIdx.x;
    const int i0 = blockIdx.y * TI;
    const int j0 = blockIdx.x * TJ;

    // stage via cp.async (dst rows 272B -> 16B aligned)
    #pragma unroll
    for (int k = tid; k < TI * 16; k += 128) {
        int r = k >> 4, c4 = (k & 15) << 2;
        cpa16(s2u(&Us[r * ST + c4]), &g_U[i0 + r][c4]);
    }
    #pragma unroll
    for (int k = tid; k < TJ * 16; k += 128) {
        int r = k >> 4, c4 = (k & 15) << 2;
        cpa16(s2u(&Vs[r * ST + c4]), &g_V[j0 + r][c4]);
    }
    if (tid < 16)
        cpa16(s2u(&w2s[tid * 4]), &W2[tid * 4]);
    asm volatile("cp.async.commit_group;");
    const float b2v = *b2;
    asm volatile("cp.async.wait_group 0;");
    __syncthreads();

    const int ig = tid & 15;    // i = ig + 16a, a<4
    const int jg = tid >> 4;    // j = jg + 8b,  b<4

    // precompute shared-space base addresses (immediate offsets carry h)
    uint32_t ub[4], vb[4];
    #pragma unroll
    for (int a = 0; a < 4; a++) ub[a] = s2u(&Us[(ig + 16 * a) * ST]);
    #pragma unroll
    for (int b = 0; b < 4; b++) vb[b] = s2u(&Vs[(jg + 8 * b) * ST]);
    const uint32_t wb = s2u(w2s);

    u64 acc[4][4];
    #pragma unroll
    for (int a = 0; a < 4; a++)
        #pragma unroll
        for (int b = 0; b < 4; b++) acc[a][b] = 0ull;

    #pragma unroll
    for (int h = 0; h < HID; h += 2) {
        const int off = h * 4;                  // byte offset
        u64 w = lds64(wb, off);
        u64 u[4], v[4];
        #pragma unroll
        for (int a = 0; a < 4; a++) u[a] = lds64(ub[a], off);
        #pragma unroll
        for (int b = 0; b < 4; b++) v[b] = lds64(vb[b], off);
        #pragma unroll
        for (int a = 0; a < 4; a++)
            #pragma unroll
            for (int b = 0; b < 4; b++)
                acc[a][b] = fma2(relu2(add2(u[a], v[b])), w, acc[a][b]);
    }
    __syncthreads();   // done reading Us before reuse as staging

    // epilogue: horizontal add, smem stage, coalesced float4 stores
    float* outS = Us;   // 64*36 floats <= 64*68
    #pragma unroll
    for (int a = 0; a < 4; a++)
        #pragma unroll
        for (int b = 0; b < 4; b++) {
            float2 p = up2(acc[a][b]);
            outS[(ig + 16 * a) * OT + (jg + 8 * b)] = p.x + p.y + b2v;
        }
    __syncthreads();
    #pragma unroll
    for (int k = tid; k < TI * 8; k += 128) {
        int r = k >> 3, c4 = (k & 7) << 2;
        *(float4*)&out[(u64)(i0 + r) * NPIX + j0 + c4] = *(const float4*)&outS[r * OT + c4];
    }
}

// ---------------------------------------------------------------------------
extern "C" void kernel_launch(void* const* d_in, const int* in_sizes, int n_in,
                              void* d_out, int out_size) {
    // 0:h 1:w 2:q_mod 3:k_mod 4:structure_map 5:mod_embed 6:W1 7:b1 8:W2 9:b2
    const int*   qmod = (const int*)d_in[2];
    const int*   kmod = (const int*)d_in[3];
    const float* smap = (const float*)d_in[4];
    const float* memb = (const float*)d_in[5];
    const float* W1   = (const float*)d_in[6];
    const float* b1   = (const float*)d_in[7];
    const float* W2   = (const float*)d_in[8];
    const float* b2   = (const float*)d_in[9];
    float* out = (float*)d_out;

    prep_kernel<<<NPIX / 16, 128>>>(qmod, kmod, smap, memb, W1, b1);

    dim3 grid(NPIX / TJ, NPIX / TI);   // 50 x 25 = 1250 blocks
    rpe_main_kernel<<<grid, 128>>>(out, W2, b2);
}

// round 12
// speedup vs baseline: 1.2347x; 1.0755x over previous
#include <cuda_runtime.h>
#include <cstdint>

#define NPIX  1600
#define WIDTH 40
#define HID   64
#define TI    64
#define TJ    32
#define ST    68       // 272B rows: 16B-aligned, conflict-free LDS.128/LDS.64
#define OT    36

typedef unsigned long long u64;

__device__ float g_U[NPIX][HID];
__device__ float g_V[NPIX][HID];

// ---- packed f32x2 helpers ----
static __device__ __forceinline__ u64 add2(u64 a, u64 b) {
    u64 r; asm("add.rn.f32x2 %0, %1, %2;" : "=l"(r) : "l"(a), "l"(b)); return r;
}
static __device__ __forceinline__ u64 fma2(u64 a, u64 b, u64 c) {
    u64 r; asm("fma.rn.f32x2 %0, %1, %2, %3;" : "=l"(r) : "l"(a), "l"(b), "l"(c)); return r;
}
static __device__ __forceinline__ float2 up2(u64 v) {
    float2 r; asm("mov.b64 {%0, %1}, %2;" : "=f"(r.x), "=f"(r.y) : "l"(v)); return r;
}
static __device__ __forceinline__ u64 pk2(float a, float b) {
    u64 r; asm("mov.b64 %0, {%1, %2};" : "=l"(r) : "f"(a), "f"(b)); return r;
}
static __device__ __forceinline__ u64 relu2(u64 v) {
    float2 t = up2(v);
    return pk2(fmaxf(t.x, 0.0f), fmaxf(t.y, 0.0f));
}
static __device__ __forceinline__ uint32_t s2u(const void* p) {
    return (uint32_t)__cvta_generic_to_shared(p);
}
static __device__ __forceinline__ void cpa16(uint32_t dst, const void* src) {
    asm volatile("cp.async.cg.shared.global [%0], [%1], 16;" :: "r"(dst), "l"(src));
}

// ---------------------------------------------------------------------------
// prep: 100 blocks x 128 threads, 16 pixels each (R11 version — 1.9us gap).
// ---------------------------------------------------------------------------
__global__ void __launch_bounds__(128) prep_kernel(
    const int* __restrict__ qmod_p, const int* __restrict__ kmod_p,
    const float* __restrict__ smap,      // (4,1,80,80)
    const float* __restrict__ memb,      // (3,16)
    const float* __restrict__ W1,        // (36,64)
    const float* __restrict__ b1)        // (64,)
{
    __shared__ float part[16][5];
    __shared__ float s_sh[16];
    __shared__ float mv[32];
    __shared__ float Cs[HID];

    const int tid = threadIdx.x;
    const int n0  = blockIdx.x * 16;
    const float raw[4] = {0.25f, 0.75f, 0.75f, 0.25f};

    if (tid >= 64 && tid < 96) {
        int t = tid - 64;
        int m = (t < 16) ? *qmod_p : *kmod_p;
        mv[t] = memb[m * 16 + (t & 15)];
    }

    if (tid < 64) {   // one (pixel,batch) per thread, 16 taps
        const int pix = tid >> 2, bb = tid & 3;
        const int n = n0 + pix;
        const int r = n / WIDTH, c = n % WIDTH;
        const float* base = smap + bb * 6400;
        float acc = 0.f;
        #pragma unroll
        for (int ty = 0; ty < 4; ty++) {
            int iy = 2 * r - 1 + ty;
            if (iy < 0 || iy >= 80) continue;
            #pragma unroll
            for (int tx = 0; tx < 4; tx++) {
                int ix = 2 * c - 1 + tx;
                if (ix < 0 || ix >= 80) continue;
                acc += raw[ty] * raw[tx] * base[iy * 80 + ix];
            }
        }
        part[pix][bb] = acc;
    }
    __syncthreads();

    if (tid < HID) {                      // C[h]
        float cc = b1[tid];
        #pragma unroll
        for (int k = 0; k < 32; k++)
            cc += mv[k] * W1[(2 + k) * HID + tid];
        Cs[tid] = cc;
    } else if (tid < 80) {                // finalize s (edge renorm, batch mean)
        const int p = tid - 64;
        const int n = n0 + p;
        const int r = n / WIDTH, c = n % WIDTH;
        float sy = 0.f, sx = 0.f;
        #pragma unroll
        for (int q = 0; q < 4; q++) {
            int iy = 2 * r - 1 + q; if (iy >= 0 && iy < 80) sy += raw[q];
            int ix = 2 * c - 1 + q; if (ix >= 0 && ix < 80) sx += raw[q];
        }
        s_sh[p] = (part[p][0] + part[p][1] + part[p][2] + part[p][3])
                  / (sy * sx) * 0.25f;
    }
    __syncthreads();

    {   // U and V rows (h-coalesced), 8 n's per thread
        const int hh = tid & 63, ng = tid >> 6;
        const float w0  = W1[hh];
        const float w1  = W1[HID + hh];
        const float wsi = W1[34 * HID + hh];
        const float wsj = W1[35 * HID + hh];
        const float ch  = Cs[hh];
        #pragma unroll
        for (int k = 0; k < 8; k++) {
            int nn = ng * 8 + k;
            int n = n0 + nn;
            int r = n / WIDTH, c = n % WIDTH;
            float x = (float)c * (1.0f / 39.0f) - 0.5f;
            float y = (float)r * (1.0f / 39.0f) - 0.5f;
            float s = s_sh[nn];
            float xy = x * w0 + y * w1;
            g_U[n][hh] =  xy + s * wsi + ch;
            g_V[n][hh] = -xy + s * wsj;
        }
    }
}

// ---------------------------------------------------------------------------
// main: 625 blocks x 128 threads. Each block: one 64-row i-strip x TWO 32-col
// j-tiles. Us staged once; Vs double-buffered (tile1's V overlaps tile0's
// compute). Inner loop = R7's proven LDS.128 h-quad loop.
// ---------------------------------------------------------------------------
__global__ void __launch_bounds__(128) rpe_main_kernel(
    float* __restrict__ out,
    const float* __restrict__ W2,    // (64,)
    const float* __restrict__ b2)    // (1,)
{
    __shared__ float Us[TI * ST];        // 17408 B
    __shared__ float Vs[2 * TJ * ST];    // 17408 B
    __shared__ float outS[TI * OT];      //  9216 B
    __shared__ float w2s[HID];           //   256 B

    const int tid = threadIdx.x;
    const int i0 = blockIdx.y * TI;
    const int j0base = blockIdx.x * (2 * TJ);

    // group A: Us + Vs[0] + w2
    #pragma unroll
    for (int k = tid; k < TI * 16; k += 128) {
        int r = k >> 4, c4 = (k & 15) << 2;
        cpa16(s2u(&Us[r * ST + c4]), &g_U[i0 + r][c4]);
    }
    #pragma unroll
    for (int k = tid; k < TJ * 16; k += 128) {
        int r = k >> 4, c4 = (k & 15) << 2;
        cpa16(s2u(&Vs[r * ST + c4]), &g_V[j0base + r][c4]);
    }
    if (tid < 16)
        cpa16(s2u(&w2s[tid * 4]), &W2[tid * 4]);
    asm volatile("cp.async.commit_group;");

    // group B: Vs[1] (prefetch, overlaps tile-0 compute)
    #pragma unroll
    for (int k = tid; k < TJ * 16; k += 128) {
        int r = k >> 4, c4 = (k & 15) << 2;
        cpa16(s2u(&Vs[TJ * ST + r * ST + c4]), &g_V[j0base + TJ + r][c4]);
    }
    asm volatile("cp.async.commit_group;");

    const float b2v = *b2;
    asm volatile("cp.async.wait_group 1;");   // group A complete
    __syncthreads();

    const int ig = tid & 15;    // i = ig + 16a, a<4
    const int jg = tid >> 4;    // j = jg + 8b,  b<4

    #pragma unroll 1
    for (int t = 0; t < 2; t++) {
        const float* Vst = &Vs[t * TJ * ST];

        u64 acc[4][4];
        #pragma unroll
        for (int a = 0; a < 4; a++)
            #pragma unroll
            for (int b = 0; b < 4; b++) acc[a][b] = 0ull;

        #pragma unroll 2
        for (int h = 0; h < HID; h += 4) {
            ulonglong2 w = *(const ulonglong2*)&w2s[h];
            ulonglong2 u[4], v[4];
            #pragma unroll
            for (int a = 0; a < 4; a++)
                u[a] = *(const ulonglong2*)&Us[(ig + 16 * a) * ST + h];
            #pragma unroll
            for (int b = 0; b < 4; b++)
                v[b] = *(const ulonglong2*)&Vst[(jg + 8 * b) * ST + h];
            #pragma unroll
            for (int a = 0; a < 4; a++)
                #pragma unroll
                for (int b = 0; b < 4; b++) {
                    acc[a][b] = fma2(relu2(add2(u[a].x, v[b].x)), w.x, acc[a][b]);
                    acc[a][b] = fma2(relu2(add2(u[a].y, v[b].y)), w.y, acc[a][b]);
                }
        }

        if (t == 0)
            asm volatile("cp.async.wait_group 0;");   // Vs[1] landed
        __syncthreads();   // t=0: Vs[1] visible; t=1: prior outS reads done

        // epilogue: horizontal add -> outS -> coalesced float4 stores
        #pragma unroll
        for (int a = 0; a < 4; a++)
            #pragma unroll
            for (int b = 0; b < 4; b++) {
                float2 p = up2(acc[a][b]);
                outS[(ig + 16 * a) * OT + (jg + 8 * b)] = p.x + p.y + b2v;
            }
        __syncthreads();
        const int jout = j0base + t * TJ;
        #pragma unroll
        for (int k = tid; k < TI * 8; k += 128) {
            int r = k >> 3, c4 = (k & 7) << 2;
            *(float4*)&out[(u64)(i0 + r) * NPIX + jout + c4] =
                *(const float4*)&outS[r * OT + c4];
        }
    }
}

// ---------------------------------------------------------------------------
extern "C" void kernel_launch(void* const* d_in, const int* in_sizes, int n_in,
                              void* d_out, int out_size) {
    // 0:h 1:w 2:q_mod 3:k_mod 4:structure_map 5:mod_embed 6:W1 7:b1 8:W2 9:b2
    const int*   qmod = (const int*)d_in[2];
    const int*   kmod = (const int*)d_in[3];
    const float* smap = (const float*)d_in[4];
    const float* memb = (const float*)d_in[5];
    const float* W1   = (const float*)d_in[6];
    const float* b1   = (const float*)d_in[7];
    const float* W2   = (const float*)d_in[8];
    const float* b2   = (const float*)d_in[9];
    float* out = (float*)d_out;

    prep_kernel<<<NPIX / 16, 128>>>(qmod, kmod, smap, memb, W1, b1);

    dim3 grid(NPIX / (2 * TJ), NPIX / TI);   // 25 x 25 = 625 blocks
    rpe_main_kernel<<<grid, 128>>>(out, W2, b2);
}

// round 13
// speedup vs baseline: 1.3355x; 1.0816x over previous
#include <cuda_runtime.h>
#include <cstdint>

#define NPIX  1600
#define WIDTH 40
#define HID   64
#define TI    64
#define TJ    32
#define ST    68       // 272B rows: 16B-aligned for cp.async, conflict-free LDS.128
#define OT    36

typedef unsigned long long u64;

__device__ float g_U[NPIX][HID];
__device__ float g_V[NPIX][HID];

// ---- packed f32x2 helpers ----
static __device__ __forceinline__ u64 add2(u64 a, u64 b) {
    u64 r; asm("add.rn.f32x2 %0, %1, %2;" : "=l"(r) : "l"(a), "l"(b)); return r;
}
static __device__ __forceinline__ u64 fma2(u64 a, u64 b, u64 c) {
    u64 r; asm("fma.rn.f32x2 %0, %1, %2, %3;" : "=l"(r) : "l"(a), "l"(b), "l"(c)); return r;
}
static __device__ __forceinline__ float2 up2(u64 v) {
    float2 r; asm("mov.b64 {%0, %1}, %2;" : "=f"(r.x), "=f"(r.y) : "l"(v)); return r;
}
static __device__ __forceinline__ u64 pk2(float a, float b) {
    u64 r; asm("mov.b64 %0, {%1, %2};" : "=l"(r) : "f"(a), "f"(b)); return r;
}
static __device__ __forceinline__ u64 relu2(u64 v) {
    float2 t = up2(v);
    return pk2(fmaxf(t.x, 0.0f), fmaxf(t.y, 0.0f));
}
static __device__ __forceinline__ uint32_t s2u(const void* p) {
    return (uint32_t)__cvta_generic_to_shared(p);
}
static __device__ __forceinline__ void cpa16(uint32_t dst, const void* src) {
    asm volatile("cp.async.cg.shared.global [%0], [%1], 16;" :: "r"(dst), "l"(src));
}

// ---------------------------------------------------------------------------
// prep: 100 blocks x 128 threads, 16 pixels each (R11-measured: 1.9us gap).
// ---------------------------------------------------------------------------
__global__ void __launch_bounds__(128) prep_kernel(
    const int* __restrict__ qmod_p, const int* __restrict__ kmod_p,
    const float* __restrict__ smap,      // (4,1,80,80)
    const float* __restrict__ memb,      // (3,16)
    const float* __restrict__ W1,        // (36,64)
    const float* __restrict__ b1)        // (64,)
{
    __shared__ float part[16][5];
    __shared__ float s_sh[16];
    __shared__ float mv[32];
    __shared__ float Cs[HID];

    const int tid = threadIdx.x;
    const int n0  = blockIdx.x * 16;
    const float raw[4] = {0.25f, 0.75f, 0.75f, 0.25f};

    if (tid >= 64 && tid < 96) {
        int t = tid - 64;
        int m = (t < 16) ? *qmod_p : *kmod_p;
        mv[t] = memb[m * 16 + (t & 15)];
    }

    if (tid < 64) {   // one (pixel,batch) per thread, 16 taps
        const int pix = tid >> 2, bb = tid & 3;
        const int n = n0 + pix;
        const int r = n / WIDTH, c = n % WIDTH;
        const float* base = smap + bb * 6400;
        float acc = 0.f;
        #pragma unroll
        for (int ty = 0; ty < 4; ty++) {
            int iy = 2 * r - 1 + ty;
            if (iy < 0 || iy >= 80) continue;
            #pragma unroll
            for (int tx = 0; tx < 4; tx++) {
                int ix = 2 * c - 1 + tx;
                if (ix < 0 || ix >= 80) continue;
                acc += raw[ty] * raw[tx] * base[iy * 80 + ix];
            }
        }
        part[pix][bb] = acc;
    }
    __syncthreads();

    if (tid < HID) {                      // C[h]
        float cc = b1[tid];
        #pragma unroll
        for (int k = 0; k < 32; k++)
            cc += mv[k] * W1[(2 + k) * HID + tid];
        Cs[tid] = cc;
    } else if (tid < 80) {                // finalize s (edge renorm, batch mean)
        const int p = tid - 64;
        const int n = n0 + p;
        const int r = n / WIDTH, c = n % WIDTH;
        float sy = 0.f, sx = 0.f;
        #pragma unroll
        for (int q = 0; q < 4; q++) {
            int iy = 2 * r - 1 + q; if (iy >= 0 && iy < 80) sy += raw[q];
            int ix = 2 * c - 1 + q; if (ix >= 0 && ix < 80) sx += raw[q];
        }
        s_sh[p] = (part[p][0] + part[p][1] + part[p][2] + part[p][3])
                  / (sy * sx) * 0.25f;
    }
    __syncthreads();

    {   // U and V rows (h-coalesced), 8 n's per thread
        const int hh = tid & 63, ng = tid >> 6;
        const float w0  = W1[hh];
        const float w1  = W1[HID + hh];
        const float wsi = W1[34 * HID + hh];
        const float wsj = W1[35 * HID + hh];
        const float ch  = Cs[hh];
        #pragma unroll
        for (int k = 0; k < 8; k++) {
            int nn = ng * 8 + k;
            int n = n0 + nn;
            int r = n / WIDTH, c = n % WIDTH;
            float x = (float)c * (1.0f / 39.0f) - 0.5f;
            float y = (float)r * (1.0f / 39.0f) - 0.5f;
            float s = s_sh[nn];
            float xy = x * w0 + y * w1;
            g_U[n][hh] =  xy + s * wsi + ch;
            g_V[n][hh] = -xy + s * wsj;
        }
    }
}

// ---------------------------------------------------------------------------
// main: R7-proven kernel. 64x32 tile, 128 threads, 4i x 4j per thread,
// packed f32x2 over h, cp.async staging, 7 blocks/SM. Measured 21.1us.
// ---------------------------------------------------------------------------
__global__ void __launch_bounds__(128, 7) rpe_main_kernel(
    float* __restrict__ out,
    const float* __restrict__ W2,    // (64,)
    const float* __restrict__ b2)    // (1,)
{
    __shared__ float Us[TI * ST];
    __shared__ float Vs[TJ * ST];
    __shared__ float w2s[HID];

    const int tid = threadIdx.x;
    const int i0 = blockIdx.y * TI;
    const int j0 = blockIdx.x * TJ;

    #pragma unroll
    for (int k = tid; k < TI * 16; k += 128) {
        int r = k >> 4, c4 = (k & 15) << 2;
        cpa16(s2u(&Us[r * ST + c4]), &g_U[i0 + r][c4]);
    }
    #pragma unroll
    for (int k = tid; k < TJ * 16; k += 128) {
        int r = k >> 4, c4 = (k & 15) << 2;
        cpa16(s2u(&Vs[r * ST + c4]), &g_V[j0 + r][c4]);
    }
    if (tid < 16)
        cpa16(s2u(&w2s[tid * 4]), &W2[tid * 4]);
    asm volatile("cp.async.commit_group;");
    const float b2v = *b2;              // overlaps with async copies
    asm volatile("cp.async.wait_group 0;");
    __syncthreads();

    const int ig = tid & 15;    // i = ig + 16a, a<4
    const int jg = tid >> 4;    // j = jg + 8b,  b<4

    u64 acc[4][4];
    #pragma unroll
    for (int a = 0; a < 4; a++)
        #pragma unroll
        for (int b = 0; b < 4; b++) acc[a][b] = 0ull;

    #pragma unroll 2
    for (int h = 0; h < HID; h += 4) {
        ulonglong2 w = *(const ulonglong2*)&w2s[h];
        ulonglong2 u[4], v[4];
        #pragma unroll
        for (int a = 0; a < 4; a++)
            u[a] = *(const ulonglong2*)&Us[(ig + 16 * a) * ST + h];
        #pragma unroll
        for (int b = 0; b < 4; b++)
            v[b] = *(const ulonglong2*)&Vs[(jg + 8 * b) * ST + h];
        #pragma unroll
        for (int a = 0; a < 4; a++)
            #pragma unroll
            for (int b = 0; b < 4; b++) {
                acc[a][b] = fma2(relu2(add2(u[a].x, v[b].x)), w.x, acc[a][b]);
                acc[a][b] = fma2(relu2(add2(u[a].y, v[b].y)), w.y, acc[a][b]);
            }
    }
    __syncthreads();   // done reading Us before reuse as staging

    // epilogue: horizontal add, smem stage, coalesced float4 stores
    float* outS = Us;   // 64*36 floats <= 64*68
    #pragma unroll
    for (int a = 0; a < 4; a++)
        #pragma unroll
        for (int b = 0; b < 4; b++) {
            float2 p = up2(acc[a][b]);
            outS[(ig + 16 * a) * OT + (jg + 8 * b)] = p.x + p.y + b2v;
        }
    __syncthreads();
    #pragma unroll
    for (int k = tid; k < TI * 8; k += 128) {
        int r = k >> 3, c4 = (k & 7) << 2;
        *(float4*)&out[(u64)(i0 + r) * NPIX + j0 + c4] = *(const float4*)&outS[r * OT + c4];
    }
}

// ---------------------------------------------------------------------------
extern "C" void kernel_launch(void* const* d_in, const int* in_sizes, int n_in,
                              void* d_out, int out_size) {
    // 0:h 1:w 2:q_mod 3:k_mod 4:structure_map 5:mod_embed 6:W1 7:b1 8:W2 9:b2
    const int*   qmod = (const int*)d_in[2];
    const int*   kmod = (const int*)d_in[3];
    const float* smap = (const float*)d_in[4];
    const float* memb = (const float*)d_in[5];
    const float* W1   = (const float*)d_in[6];
    const float* b1   = (const float*)d_in[7];
    const float* W2   = (const float*)d_in[8];
    const float* b2   = (const float*)d_in[9];
    float* out = (float*)d_out;

    prep_kernel<<<NPIX / 16, 128>>>(qmod, kmod, smap, memb, W1, b1);

    dim3 grid(NPIX / TJ, NPIX / TI);   // 50 x 25 = 1250 blocks
    rpe_main_kernel<<<grid, 128>>>(out, W2, b2);
}